// round 7
// baseline (speedup 1.0000x reference)
#include <cuda_runtime.h>

typedef unsigned long long u64;
typedef unsigned int u32;

#define DD 1024
#define TT 256
#define BB 64
#define BETA_W 0.001f

__device__ __forceinline__ u64 ce_sel(u64 a, u64 b, bool takeMax) {
    return takeMax ? (a > b ? a : b) : (a < b ? a : b);
}

// intra-thread + intra-warp bitonic substeps: j = jstart..1 for stage k
__device__ __forceinline__ void intra_stage(u64 v[4], int tid, int k, int jstart) {
    for (int j = jstart; j >= 4; j >>= 1) {       // shfl steps (lane delta j/4)
        int ld = j >> 2;
        #pragma unroll
        for (int q = 0; q < 4; q++) {
            u64 o = __shfl_xor_sync(0xffffffffu, v[q], ld);
            int g = (tid << 2) | q;
            v[q] = ce_sel(v[q], o, ((g & j) == 0) == ((g & k) == 0));
        }
    }
    if (jstart >= 2) {                            // j=2: pairs (0,2),(1,3)
        #pragma unroll
        for (int q = 0; q < 2; q++) {
            int ga = (tid << 2) | q;
            bool dec = ((ga & k) == 0);
            u64 A = v[q], B = v[q + 2];
            u64 mx = A > B ? A : B, mn = A > B ? B : A;
            v[q] = dec ? mx : mn; v[q + 2] = dec ? mn : mx;
        }
    }
    #pragma unroll
    for (int q = 0; q < 4; q += 2) {              // j=1: pairs (0,1),(2,3)
        int ga = (tid << 2) | q;
        bool dec = ((ga & k) == 0);
        u64 A = v[q], B = v[q + 1];
        u64 mx = A > B ? A : B, mn = A > B ? B : A;
        v[q] = dec ? mx : mn; v[q + 1] = dec ? mn : mx;
    }
}

__device__ __forceinline__ void publish(u64 v[4], u64* buf, int tid) {
    #pragma unroll
    for (int q = 0; q < 4; q++) buf[(tid << 2) | q] = v[q];
}

__device__ __forceinline__ void cross_step(u64 v[4], const u64* buf, int tid, int j, int k) {
    #pragma unroll
    for (int q = 0; q < 4; q++) {
        int g = (tid << 2) | q;
        u64 o = buf[g ^ j];
        v[q] = ce_sel(v[q], o, ((g & j) == 0) == ((g & k) == 0));
    }
}

// Junction cascade over a gapped block array with edge pointers.
__device__ void cascade(float2* b, int* jl, int* jr, int ls, int junc, int re) {
    int li = junc - 1;
    float2 L = b[li];
    if (L.y == 0.0f) { li = jl[li]; L = b[li]; }
    float2 P = b[junc];
    if (!(L.x * P.y < P.x * L.y)) return;
    P.x += L.x; P.y += L.y;
    b[li].y = 0.0f;
    b[junc].y = 0.0f;
    int lpos = li;
    int lc = li - 1;
    int rc = junc + 1;
    int lstop = ls - 1;
    int rstop = re;
    bool changed = true;
    while (changed) {
        changed = false;
        while (lc >= ls) {
            float2 Lb = b[lc];
            if (Lb.y == 0.0f) { lc = jl[lc]; if (lc < ls) break; Lb = b[lc]; }
            if (Lb.x * P.y < P.x * Lb.y) {
                P.x += Lb.x; P.y += Lb.y;
                b[lc].y = 0.0f;
                lpos = lc; --lc; changed = true;
            } else { lstop = lc; break; }
        }
        while (rc < re) {
            float2 Rb = b[rc];
            if (Rb.y == 0.0f) { rc = jr[rc]; if (rc >= re) break; Rb = b[rc]; }
            if (Rb.x * P.y > P.x * Rb.y) {
                P.x += Rb.x; P.y += Rb.y;
                b[rc].y = 0.0f;
                ++rc; changed = true;
            } else { rstop = rc; break; }
        }
    }
    b[lpos] = P;
    if (lpos - 1 > lstop) { jl[lpos - 1] = lstop; jr[lstop + 1] = lpos; }
    if (rstop - 1 > lpos) { jl[rstop - 1] = lpos; jr[lpos + 1] = rstop; }
}

__global__ __launch_bounds__(TT) void oscarmax_kernel(const float* __restrict__ x,
                                                      float* __restrict__ out) {
    __shared__ u64   sbuf[2][DD];      // sort buffers; after: bA (sbuf[0]) + jl/jr (sbuf[1])
    __shared__ float sy[DD];
    __shared__ float mval[DD];
    __shared__ float sgn_mark[DD];     // sign(x); then markerpos (int view)
    __shared__ float zcs[DD];
    __shared__ int   part_a[8];
    __shared__ int   part_b[8];
    __shared__ int   part_c[8];
    __shared__ float part_d[8];
    __shared__ int   ksup_sh;

    int*    markerpos = (int*)sgn_mark;
    float2* bA = (float2*)&sbuf[0][0];
    int*    jl = (int*)&sbuf[1][0];
    int*    jr = jl + DD;
    u64*    b0 = &sbuf[0][0];
    u64*    b1 = &sbuf[1][0];

    const int tid  = threadIdx.x;
    const int lane = tid & 31;
    const int wrp  = tid >> 5;
    const int row  = blockIdx.x;

    // ---- load 4 elems (float4), signs, pack sortable u64 ----
    float4 xl = ((const float4*)(x + row * DD))[tid];
    float xs[4] = {xl.x, xl.y, xl.z, xl.w};
    u64 v[4];
    {
        float4 sg;
        sg.x = (xs[0] > 0.0f) ? 1.0f : ((xs[0] < 0.0f) ? -1.0f : 0.0f);
        sg.y = (xs[1] > 0.0f) ? 1.0f : ((xs[1] < 0.0f) ? -1.0f : 0.0f);
        sg.z = (xs[2] > 0.0f) ? 1.0f : ((xs[2] < 0.0f) ? -1.0f : 0.0f);
        sg.w = (xs[3] > 0.0f) ? 1.0f : ((xs[3] < 0.0f) ? -1.0f : 0.0f);
        ((float4*)sgn_mark)[tid] = sg;
        #pragma unroll
        for (int q = 0; q < 4; q++) {
            u32 kb = __float_as_uint(fabsf(xs[q]));
            v[q] = ((u64)kb << 32) | (u32)(~(u32)((tid << 2) | q));
        }
    }

    // ---- bitonic sort, descending; k=2..128 fully barrier-free ----
    #pragma unroll 1
    for (int k = 2; k <= 128; k <<= 1) intra_stage(v, tid, k, k >> 1);
    // k=256
    publish(v, b0, tid); __syncthreads();
    cross_step(v, b0, tid, 128, 256);
    intra_stage(v, tid, 256, 64);
    // k=512
    publish(v, b1, tid); __syncthreads();
    cross_step(v, b1, tid, 256, 512);
    publish(v, b0, tid); __syncthreads();
    cross_step(v, b0, tid, 128, 512);
    intra_stage(v, tid, 512, 64);
    // k=1024
    publish(v, b1, tid); __syncthreads();
    cross_step(v, b1, tid, 512, 1024);
    publish(v, b0, tid); __syncthreads();
    cross_step(v, b0, tid, 256, 1024);
    publish(v, b1, tid); __syncthreads();
    cross_step(v, b1, tid, 128, 1024);
    intra_stage(v, tid, 1024, 64);

    // ---- unpack, gather signs, write s ----
    int   idxq[4];
    float sgnq[4];
    {
        float4 s4;
        float* sp = (float*)&s4;
        #pragma unroll
        for (int q = 0; q < 4; q++) {
            int g = (tid << 2) | q;
            float keyf = __uint_as_float((u32)(v[q] >> 32));
            idxq[q] = (int)(~((u32)v[q]));
            sgnq[q] = sgn_mark[idxq[q]];
            sp[q] = keyf - BETA_W * (float)(DD - 1 - g);
        }
        ((float4*)sy)[tid] = s4;
    }
    __syncthreads();    // sy visible; sgn reads done; sort buffers dead

    if (tid == 0) ksup_sh = 0;
    ((int4*)markerpos)[tid] = make_int4(-1, -1, -1, -1);

    // ---- per-chunk PAVA: 32 runners (tid%8==0), chunk = tid/8 ----
    if ((tid & 7) == 0) {
        const int base = (tid >> 3) << 5;
        float2* cb = bA + base;
        int nb = 0;
        float ts = sy[base], tc = 1.0f;
        #pragma unroll 1
        for (int i = 1; i < 32; i++) {
            float cs = sy[base + i], cc = 1.0f;
            for (;;) {
                if (cs * tc > ts * cc) {
                    cs += ts; cc += tc;
                    if (nb > 0) { --nb; ts = cb[nb].x; tc = cb[nb].y; }
                    else        { ts = cs; tc = cc; goto nexti; }
                } else break;
            }
            cb[nb++] = make_float2(ts, tc);
            ts = cs; tc = cc;
            nexti: ;
        }
        cb[nb++] = make_float2(ts, tc);
        for (int q = nb; q < 32; q++) cb[q].y = 0.0f;
        if (nb < 32) {
            jl[base + 31] = base + nb - 1;
            jr[base + nb] = base + 32;
        }
    }
    __syncthreads();

    // ---- merge tree: 5 cascade levels in warp 0 ----
    if (wrp == 0) {
        #pragma unroll 1
        for (int L = 0; L < 5; L++) {
            int npairs = 16 >> L;
            if (lane < npairs) {
                int seg = 64 << L;
                int ls  = lane * seg;
                cascade(bA, jl, jr, ls, ls + (seg >> 1), ls + seg);
            }
            __syncwarp();
        }
    }
    __syncthreads();

    // ---- expansion: block exclusive scan of block counts ----
    {
        float2 bf[4]; int cq[4], pre[4];
        int run = 0;
        #pragma unroll
        for (int q = 0; q < 4; q++) {
            bf[q] = bA[(tid << 2) | q];
            cq[q] = (int)bf[q].y;
            pre[q] = run; run += cq[q];
        }
        int inc = run;
        #pragma unroll
        for (int o = 1; o < 32; o <<= 1) {
            int t = __shfl_up_sync(0xffffffffu, inc, o);
            if (lane >= o) inc += t;
        }
        if (lane == 31) part_a[wrp] = inc;
        __syncthreads();
        if (tid < 32) {
            int p = (tid < 8) ? part_a[tid] : 0;
            #pragma unroll
            for (int o = 1; o < 8; o <<= 1) {
                int t = __shfl_up_sync(0xffffffffu, p, o);
                if (tid >= o) p += t;
            }
            if (tid < 8) part_a[tid] = p;
        }
        __syncthreads();
        int base = inc - run + ((wrp > 0) ? part_a[wrp - 1] : 0);
        #pragma unroll
        for (int q = 0; q < 4; q++) {
            if (cq[q] > 0) {
                int st = base + pre[q];
                mval[st] = fmaxf(bf[q].x / bf[q].y, 0.0f);
                markerpos[st] = st;
            }
        }
    }
    __syncthreads();

    // ---- fill-forward: block inclusive max-scan of markers ----
    float zq[4];
    {
        int4 ml = ((int4*)markerpos)[tid];
        int mloc[4];
        mloc[0] = ml.x;
        mloc[1] = max(mloc[0], ml.y);
        mloc[2] = max(mloc[1], ml.z);
        mloc[3] = max(mloc[2], ml.w);
        int inc = mloc[3];
        #pragma unroll
        for (int o = 1; o < 32; o <<= 1) {
            int t = __shfl_up_sync(0xffffffffu, inc, o);
            if (lane >= o) inc = max(inc, t);
        }
        int exc = __shfl_up_sync(0xffffffffu, inc, 1);
        if (lane == 0) exc = -1;
        if (lane == 31) part_b[wrp] = inc;
        __syncthreads();
        if (tid < 32) {
            int p = (tid < 8) ? part_b[tid] : -1;
            #pragma unroll
            for (int o = 1; o < 8; o <<= 1) {
                int t = __shfl_up_sync(0xffffffffu, p, o);
                if (tid >= o) p = max(p, t);
            }
            if (tid < 8) part_b[tid] = p;
        }
        __syncthreads();
        int thr_excl = max(exc, (wrp > 0) ? part_b[wrp - 1] : -1);
        #pragma unroll
        for (int q = 0; q < 4; q++) {
            int mp = max(thr_excl, mloc[q]);
            zq[q] = sgnq[q] * mval[mp];
        }
    }

    // ---- sorted-z without a sort: packed (P,N) rank scan ----
    {
        int pk[4], pre[4];
        int run = 0;
        #pragma unroll
        for (int q = 0; q < 4; q++) {
            int fP = (zq[q] > 0.0f) ? 1 : 0;
            int fN = (zq[q] < 0.0f) ? 1 : 0;
            pk[q] = (fP << 16) | fN;
            pre[q] = run; run += pk[q];
        }
        int inc = run;
        #pragma unroll
        for (int o = 1; o < 32; o <<= 1) {
            int t = __shfl_up_sync(0xffffffffu, inc, o);
            if (lane >= o) inc += t;
        }
        if (lane == 31) part_c[wrp] = inc;
        __syncthreads();
        if (tid < 32) {
            int p = (tid < 8) ? part_c[tid] : 0;
            #pragma unroll
            for (int o = 1; o < 8; o <<= 1) {
                int t = __shfl_up_sync(0xffffffffu, p, o);
                if (tid >= o) p += t;
            }
            if (tid < 8) part_c[tid] = p;
        }
        __syncthreads();
        int total = part_c[7];
        int totalP = total >> 16;
        int base = inc - run + ((wrp > 0) ? part_c[wrp - 1] : 0);
        #pragma unroll
        for (int q = 0; q < 4; q++) {
            int g = (tid << 2) | q;
            int excl = base + pre[q];
            int pPex = excl >> 16;
            int pNex = excl & 0xffff;
            int pos;
            if (zq[q] > 0.0f)      pos = pPex;
            else if (zq[q] < 0.0f) pos = DD - 1 - pNex;
            else                   pos = totalP + (g - pPex - pNex);
            zcs[pos] = zq[q];
        }
    }
    __syncthreads();

    // ---- sparsemax: cumsum over sorted z, support count, tau ----
    {
        float4 zl = ((float4*)zcs)[tid];
        float zs[4] = {zl.x, zl.y, zl.z, zl.w};
        float cl[4];
        cl[0] = zs[0];
        cl[1] = cl[0] + zs[1];
        cl[2] = cl[1] + zs[2];
        cl[3] = cl[2] + zs[3];
        float inc = cl[3];
        #pragma unroll
        for (int o = 1; o < 32; o <<= 1) {
            float t = __shfl_up_sync(0xffffffffu, inc, o);
            if (lane >= o) inc += t;
        }
        if (lane == 31) part_d[wrp] = inc;
        __syncthreads();
        if (tid < 32) {
            float p = (tid < 8) ? part_d[tid] : 0.0f;
            #pragma unroll
            for (int o = 1; o < 8; o <<= 1) {
                float t = __shfl_up_sync(0xffffffffu, p, o);
                if (tid >= o) p += t;
            }
            if (tid < 8) part_d[tid] = p;
        }
        __syncthreads();
        float off = (inc - cl[3]) + ((wrp > 0) ? part_d[wrp - 1] : 0.0f);
        int lc = 0;
        float4 cw;
        float* cwp = (float*)&cw;
        #pragma unroll
        for (int q = 0; q < 4; q++) {
            int g = (tid << 2) | q;
            float c = off + cl[q];
            cwp[q] = c;
            if (1.0f + (float)(g + 1) * zs[q] > c) lc++;
        }
        ((float4*)zcs)[tid] = cw;
        if (lc) atomicAdd(&ksup_sh, lc);
        __syncthreads();
        int k_sup = ksup_sh;
        float tau = (zcs[k_sup - 1] - 1.0f) / (float)k_sup;
        #pragma unroll
        for (int q = 0; q < 4; q++) {
            out[row * DD + idxq[q]] = fmaxf(zq[q] - tau, 0.0f);
        }
    }
}

extern "C" void kernel_launch(void* const* d_in, const int* in_sizes, int n_in,
                              void* d_out, int out_size) {
    const float* x = (const float*)d_in[0];
    float* out = (float*)d_out;
    oscarmax_kernel<<<BB, TT>>>(x, out);
}